// round 16
// baseline (speedup 1.0000x reference)
#include <cuda_runtime.h>
#include <cuda_bf16.h>
#include <math.h>
#include <stdint.h>

// ---------------------------------------------------------------------------
// VectorQuantizerEMA (N=32768, K=8192, D=512)
// bf16 mma.sync GEMM (exact -|e|^2/2 in acc init) + global top-4 exact
// rescore with fused scatter. R16: stats reduce folded into refine last-block.
// ---------------------------------------------------------------------------
#define NTOK 32768
#define KCODE 8192
#define DDIM 512

#define DECAY 0.99f
#define ONE_MINUS_DECAY 0.01f
#define EPS 1e-5f
#define COMMIT 0.25f

#define OQ  ((size_t)0)
#define OL  ((size_t)(NTOK) * DDIM)
#define OP  (OL + 1)
#define OE  (OP + 1)
#define OC  (OE + (size_t)KCODE * DDIM)
#define OW  (OC + KCODE)

// ------------------------- device scratch (no alloc) -----------------------
__device__ float                        g_halfE2[KCODE];
__device__ float                        g_cs[KCODE];
__device__ __align__(256) float         g_dw[(size_t)KCODE * DDIM];
__device__ double                       g_loss;
__device__ double                       g_tot_pre;
__device__ double                       g_tot_ent;
__device__ unsigned int                 g_done;
__device__ __align__(256) __nv_bfloat16 g_xb[(size_t)NTOK * DDIM];
__device__ __align__(256) __nv_bfloat16 g_eb[(size_t)KCODE * DDIM];
__device__ float4                       g_cand[(size_t)NTOK * 64]; // [token][ct]

// ------------------------- helpers -----------------------------------------
__device__ __forceinline__ uint32_t smem_u32(const void* p) {
    uint32_t a;
    asm("{ .reg .u64 t; cvta.to.shared.u64 t, %1; cvt.u32.u64 %0, t; }" : "=r"(a) : "l"(p));
    return a;
}
__device__ __forceinline__ void cp16(uint32_t dst, const void* src) {
    asm volatile("cp.async.cg.shared.global [%0], [%1], 16;" :: "r"(dst), "l"(src));
}
#define CP_COMMIT() asm volatile("cp.async.commit_group;" ::: "memory")

__device__ __forceinline__ void ldm_x4(uint32_t addr, uint32_t& r0, uint32_t& r1,
                                       uint32_t& r2, uint32_t& r3) {
    asm volatile("ldmatrix.sync.aligned.m8n8.x4.shared.b16 {%0,%1,%2,%3}, [%4];"
                 : "=r"(r0), "=r"(r1), "=r"(r2), "=r"(r3) : "r"(addr));
}
__device__ __forceinline__ void mma16816(float* d, const uint32_t* a, const uint32_t* b) {
    asm volatile("mma.sync.aligned.m16n8k16.row.col.f32.bf16.bf16.f32 "
                 "{%0,%1,%2,%3}, {%4,%5,%6,%7}, {%8,%9}, {%0,%1,%2,%3};"
                 : "+f"(d[0]), "+f"(d[1]), "+f"(d[2]), "+f"(d[3])
                 : "r"(a[0]), "r"(a[1]), "r"(a[2]), "r"(a[3]), "r"(b[0]), "r"(b[1]));
}
// vectorized global reduction (sm_90+): 1 REDG op for 4 floats
__device__ __forceinline__ void redg_v4(float* ptr, float a, float b, float c, float d) {
    asm volatile("red.global.add.v4.f32 [%0], {%1, %2, %3, %4};"
                 :: "l"(ptr), "f"(a), "f"(b), "f"(c), "f"(d) : "memory");
}
__device__ __forceinline__ void merge2(float& t1v, int& t1i, float& t2v, int& t2i,
                                       float o1v, int o1i, float o2v, int o2i) {
    if (o1v > t1v) {
        float n2v = t1v; int n2i = t1i;
        if (o2v > n2v) { n2v = o2v; n2i = o2i; }
        t1v = o1v; t1i = o1i; t2v = n2v; t2i = n2i;
    } else if (o1v > t2v) {
        t2v = o1v; t2i = o1i;
    }
}
__device__ __forceinline__ void ins4(float* v, int* ix, float ov, int oi) {
    if (ov > v[3]) {
        if (ov > v[2]) {
            v[3] = v[2]; ix[3] = ix[2];
            if (ov > v[1]) {
                v[2] = v[1]; ix[2] = ix[1];
                if (ov > v[0]) { v[1] = v[0]; ix[1] = ix[0]; v[0] = ov; ix[0] = oi; }
                else { v[1] = ov; ix[1] = oi; }
            } else { v[2] = ov; ix[2] = oi; }
        } else { v[3] = ov; ix[3] = oi; }
    }
}

// ---------------------------------------------------------------------------
// K0: merged init. Blocks [0, KCODE): E->bf16 + half-norms + zero scratch.
//     Blocks [KCODE, ...): X->bf16 (float4 wide).
// ---------------------------------------------------------------------------
#define XBLOCKS ((NTOK * DDIM / 4) / 256)   // 16384

__global__ void k_init(const float* __restrict__ E, const float* __restrict__ X) {
    int b = blockIdx.x;
    int t = threadIdx.x;
    if (b < KCODE) {
        int k = b;
        const float* row = E + (size_t)k * DDIM;
        float e0 = row[t], e1 = row[t + 256];

        g_eb[(size_t)k * DDIM + t]       = __float2bfloat16_rn(e0);
        g_eb[(size_t)k * DDIM + t + 256] = __float2bfloat16_rn(e1);

        float s = e0 * e0 + e1 * e1;
        __shared__ float sh[8];
        int lane = t & 31, w = t >> 5;
        #pragma unroll
        for (int o = 16; o; o >>= 1) s += __shfl_down_sync(0xffffffffu, s, o);
        if (lane == 0) sh[w] = s;
        __syncthreads();
        if (w == 0) {
            float v = (lane < 8) ? sh[lane] : 0.f;
            #pragma unroll
            for (int o = 4; o; o >>= 1) v += __shfl_down_sync(0xffffffffu, v, o);
            if (lane == 0) g_halfE2[k] = 0.5f * v;
        }
        float* dwr = g_dw + (size_t)k * DDIM;
        dwr[t] = 0.f;
        dwr[t + 256] = 0.f;
        if (t == 0) g_cs[k] = 0.f;
        if (k == 0 && t == 0) {
            g_loss = 0.0; g_tot_pre = 0.0; g_tot_ent = 0.0; g_done = 0u;
        }
    } else {
        size_t i = (size_t)(b - KCODE) * 256 + t;     // float4 index
        float4 x = *(const float4*)(X + i * 4);
        __nv_bfloat162 lo = __floats2bfloat162_rn(x.x, x.y);
        __nv_bfloat162 hi = __floats2bfloat162_rn(x.z, x.w);
        uint2 o;
        o.x = *(uint32_t*)&lo;
        o.y = *(uint32_t*)&hi;
        *(uint2*)(g_xb + i * 4) = o;
    }
}

// ---------------------------------------------------------------------------
// K1: persistent bf16 GEMM + per-tile top-2. (R8 structure, unchanged)
// ---------------------------------------------------------------------------
#define BM 128
#define BN 128
#define BK 32
#define KCH 16
#define NITEMS (256 * 64)
#define NCTA 296
#define SROW 40                      // bf16 stride (32 + 8 pad) = 80 B
#define STAGE_A (BM * SROW * 2)      // 10240 B
#define STAGE_SZ (2 * STAGE_A)       // 20480 B
#define NSTAGE 4
#define RED_OFF (NSTAGE * STAGE_SZ)
#define GEMM_SMEM (RED_OFF + 4096)   // 86016 B

__device__ __forceinline__ void load_flat(int gflat, int i0, uint32_t sb, int tid) {
    const int item = i0 + (gflat >> 4);
    const int kc = gflat & 15;
    const int m0 = (item >> 6) * BM;
    const int n0 = (item & 63) * BN;
    const int koff = kc * BK;
    const uint32_t stA = sb + (gflat & 3) * STAGE_SZ;
    const uint32_t stB = stA + STAGE_A;
    #pragma unroll
    for (int i = 0; i < 2; i++) {
        int idx = tid + i * 256;
        int row = idx >> 2, c = idx & 3;
        cp16(stA + row * (SROW * 2) + c * 16,
             g_xb + (size_t)(m0 + row) * DDIM + koff + c * 8);
        cp16(stB + row * (SROW * 2) + c * 16,
             g_eb + (size_t)(n0 + row) * DDIM + koff + c * 8);
    }
    CP_COMMIT();
}

__global__ __launch_bounds__(256, 2)
void k_gemm() {
    extern __shared__ char smem[];
    const uint32_t sb = smem_u32(smem);
    const int tid = threadIdx.x;
    const int wid = tid >> 5;
    const int lane = tid & 31;
    const int wm = wid >> 1;
    const int wn = wid & 1;
    const int bid = blockIdx.x;

    const int base = NITEMS / NCTA;              // 55
    const int rem  = NITEMS - base * NCTA;       // 104
    const int i0   = bid * base + (bid < rem ? bid : rem);
    const int cnt  = base + (bid < rem ? 1 : 0);
    const int T    = cnt * KCH;

    const uint32_t a_off = (uint32_t)(wm * 32 + (lane & 15)) * (SROW * 2) + (lane >> 4) * 16;
    const uint32_t b_row = (uint32_t)(wn * 64 + (lane & 7) + ((lane >> 4) << 3));
    const uint32_t b_off = b_row * (SROW * 2) + ((lane >> 3) & 1) * 16;

    load_flat(0, i0, sb, tid);
    load_flat(1, i0, sb, tid);
    load_flat(2, i0, sb, tid);

    float acc[2][8][4];

    for (int g = 0; g < T; ++g) {
        const int kc = g & 15;
        const int item = i0 + (g >> 4);
        const int n0 = (item & 63) * BN;

        if (kc == 0) {
            #pragma unroll
            for (int nf = 0; nf < 8; nf++) {
                int col = n0 + wn * 64 + nf * 8 + (lane & 3) * 2;
                float2 h = *(const float2*)(&g_halfE2[col]);
                acc[0][nf][0] = -h.x; acc[0][nf][1] = -h.y;
                acc[0][nf][2] = -h.x; acc[0][nf][3] = -h.y;
                acc[1][nf][0] = -h.x; acc[1][nf][1] = -h.y;
                acc[1][nf][2] = -h.x; acc[1][nf][3] = -h.y;
            }
        }

        const int pa = T - 1 - g;
        if (pa >= 2)      asm volatile("cp.async.wait_group 2;" ::: "memory");
        else if (pa == 1) asm volatile("cp.async.wait_group 1;" ::: "memory");
        else              asm volatile("cp.async.wait_group 0;" ::: "memory");
        __syncthreads();

        const uint32_t stA = sb + (g & 3) * STAGE_SZ;
        const uint32_t stB = stA + STAGE_A;
        #pragma unroll
        for (int ks = 0; ks < 2; ks++) {
            uint32_t a[2][4];
            ldm_x4(stA + a_off + ks * 32, a[0][0], a[0][1], a[0][2], a[0][3]);
            ldm_x4(stA + a_off + ks * 32 + 16 * (SROW * 2),
                   a[1][0], a[1][1], a[1][2], a[1][3]);
            uint32_t b[8][2];
            #pragma unroll
            for (int np = 0; np < 4; np++) {
                uint32_t r0, r1, r2, r3;
                ldm_x4(stB + b_off + ks * 32 + np * (16 * SROW * 2), r0, r1, r2, r3);
                b[np * 2][0] = r0; b[np * 2][1] = r1;
                b[np * 2 + 1][0] = r2; b[np * 2 + 1][1] = r3;
            }
            #pragma unroll
            for (int mf = 0; mf < 2; mf++)
                #pragma unroll
                for (int nf = 0; nf < 8; nf++)
                    mma16816(acc[mf][nf], a[mf], b[nf]);
        }
        if (g + 3 < T) load_flat(g + 3, i0, sb, tid);

        if (kc == KCH - 1) {
            const int m0 = (item >> 6) * BM;
            const int ct = item & 63;
            float t1v[4], t2v[4];
            int   t1i[4], t2i[4];
            #pragma unroll
            for (int s = 0; s < 4; s++) { t1v[s] = -3.0e38f; t2v[s] = -3.0e38f; t1i[s] = 0; t2i[s] = 0; }
            #pragma unroll
            for (int mf = 0; mf < 2; mf++)
                #pragma unroll
                for (int h = 0; h < 2; h++) {
                    int s = mf * 2 + h;
                    #pragma unroll
                    for (int nf = 0; nf < 8; nf++) {
                        int colb = n0 + wn * 64 + nf * 8 + (lane & 3) * 2;
                        float v0 = acc[mf][nf][h * 2 + 0];
                        float v1 = acc[mf][nf][h * 2 + 1];
                        if (v0 > t1v[s]) { t2v[s] = t1v[s]; t2i[s] = t1i[s]; t1v[s] = v0; t1i[s] = colb; }
                        else if (v0 > t2v[s]) { t2v[s] = v0; t2i[s] = colb; }
                        if (v1 > t1v[s]) { t2v[s] = t1v[s]; t2i[s] = t1i[s]; t1v[s] = v1; t1i[s] = colb + 1; }
                        else if (v1 > t2v[s]) { t2v[s] = v1; t2i[s] = colb + 1; }
                    }
                }
            #pragma unroll
            for (int s = 0; s < 4; s++) {
                #pragma unroll
                for (int d = 1; d <= 2; d <<= 1) {
                    float o1v = __shfl_xor_sync(0xffffffffu, t1v[s], d);
                    int   o1i = __shfl_xor_sync(0xffffffffu, t1i[s], d);
                    float o2v = __shfl_xor_sync(0xffffffffu, t2v[s], d);
                    int   o2i = __shfl_xor_sync(0xffffffffu, t2i[s], d);
                    merge2(t1v[s], t1i[s], t2v[s], t2i[s], o1v, o1i, o2v, o2i);
                }
            }
            __syncthreads();
            float* c_v = (float*)(smem + RED_OFF);            // [128][2][2]
            int*   c_i = (int*)(smem + RED_OFF + 2048);       // [128][2][2]
            if ((lane & 3) == 0) {
                #pragma unroll
                for (int s = 0; s < 4; s++) {
                    int mf = s >> 1, h = s & 1;
                    int row = wm * 32 + mf * 16 + h * 8 + (lane >> 2);
                    c_v[(row * 2 + wn) * 2 + 0] = t1v[s];
                    c_v[(row * 2 + wn) * 2 + 1] = t2v[s];
                    c_i[(row * 2 + wn) * 2 + 0] = t1i[s];
                    c_i[(row * 2 + wn) * 2 + 1] = t2i[s];
                }
            }
            __syncthreads();
            if (tid < BM) {
                float v1 = c_v[(tid * 2) * 2 + 0], v2 = c_v[(tid * 2) * 2 + 1];
                int   i1 = c_i[(tid * 2) * 2 + 0], i2 = c_i[(tid * 2) * 2 + 1];
                merge2(v1, i1, v2, i2,
                       c_v[(tid * 2 + 1) * 2 + 0], c_i[(tid * 2 + 1) * 2 + 0],
                       c_v[(tid * 2 + 1) * 2 + 1], c_i[(tid * 2 + 1) * 2 + 1]);
                g_cand[(size_t)(m0 + tid) * 64 + ct] =
                    make_float4(v1, v2, __int_as_float(i1), __int_as_float(i2));
            }
        }
    }
}

// ---------------------------------------------------------------------------
// K1b: merge 64 tile-candidates -> global top-4, exact fp32 rescore, fused
// scatter. Last block computes the stats reduce (deterministic single-block).
// ---------------------------------------------------------------------------
#define REFINE_BLOCKS (NTOK / 8)     // 4096

__global__ void k_refine(const float* __restrict__ X, const float* __restrict__ E,
                         const float* __restrict__ ema_cs, float* __restrict__ out) {
    const int n = blockIdx.x * 8 + (threadIdx.x >> 5);
    const int lane = threadIdx.x & 31;

    float4 cA = g_cand[(size_t)n * 64 + lane];
    float4 cB = g_cand[(size_t)n * 64 + lane + 32];

    float v[4]; int ix[4];
    v[0] = -3.0e38f; v[1] = -3.0e38f; v[2] = -3.0e38f; v[3] = -3.0e38f;
    ix[0] = ix[1] = ix[2] = ix[3] = 0;
    ins4(v, ix, cA.x, __float_as_int(cA.z));
    ins4(v, ix, cA.y, __float_as_int(cA.w));
    ins4(v, ix, cB.x, __float_as_int(cB.z));
    ins4(v, ix, cB.y, __float_as_int(cB.w));

    #pragma unroll
    for (int d = 16; d; d >>= 1) {
        float ov[4]; int oi[4];
        #pragma unroll
        for (int s = 0; s < 4; s++) {
            ov[s] = __shfl_xor_sync(0xffffffffu, v[s], d);
            oi[s] = __shfl_xor_sync(0xffffffffu, ix[s], d);
        }
        #pragma unroll
        for (int s = 0; s < 4; s++) ins4(v, ix, ov[s], oi[s]);
    }

    float4 xr[4];
    const float* x = X + (size_t)n * DDIM;
    #pragma unroll
    for (int i = 0; i < 4; i++) xr[i] = *(const float4*)(x + lane * 4 + i * 128);

    float bestv = -3.0e38f; int besti = 0x7fffffff;
    #pragma unroll
    for (int c = 0; c < 4; c++) {
        const float* e = E + (size_t)ix[c] * DDIM;
        float s = 0.f;
        #pragma unroll
        for (int i = 0; i < 4; i++) {
            float4 ev = *(const float4*)(e + lane * 4 + i * 128);
            s = fmaf(xr[i].x, ev.x, s);
            s = fmaf(xr[i].y, ev.y, s);
            s = fmaf(xr[i].z, ev.z, s);
            s = fmaf(xr[i].w, ev.w, s);
        }
        #pragma unroll
        for (int o = 16; o; o >>= 1) s += __shfl_xor_sync(0xffffffffu, s, o);
        s -= g_halfE2[ix[c]];
        if (s > bestv || (s == bestv && ix[c] < besti)) { bestv = s; besti = ix[c]; }
    }

    // ---- fused scatter ----
    const int k = besti;
    const float* e = E + (size_t)k * DDIM;
    float ls = 0.f;
    #pragma unroll
    for (int i = 0; i < 4; i++) {
        float4 q = *(const float4*)(e + lane * 4 + i * 128);
        float4 o;
        float dx = q.x - xr[i].x, dy = q.y - xr[i].y;
        float dz = q.z - xr[i].z, dw = q.w - xr[i].w;
        o.x = xr[i].x + dx; o.y = xr[i].y + dy;
        o.z = xr[i].z + dz; o.w = xr[i].w + dw;
        *(float4*)(out + OQ + (size_t)n * DDIM + lane * 4 + i * 128) = o;
        ls = fmaf(dx, dx, ls); ls = fmaf(dy, dy, ls);
        ls = fmaf(dz, dz, ls); ls = fmaf(dw, dw, ls);
        redg_v4(&g_dw[(size_t)k * DDIM + lane * 4 + i * 128],
                xr[i].x, xr[i].y, xr[i].z, xr[i].w);
    }
    #pragma unroll
    for (int o = 16; o; o >>= 1) ls += __shfl_xor_sync(0xffffffffu, ls, o);
    if (lane == 0) {
        atomicAdd(&g_loss, (double)ls);
        atomicAdd(&g_cs[k], 1.0f);
    }

    // ---- last-block stats reduce (deterministic: single block, plain store) --
    __shared__ unsigned int s_rank;
    __threadfence();
    __syncthreads();
    if (threadIdx.x == 0) s_rank = atomicAdd(&g_done, 1u);
    __syncthreads();
    if (s_rank == REFINE_BLOCKS - 1) {
        double s_pre = 0.0, s_ent = 0.0;
        #pragma unroll
        for (int i = 0; i < KCODE / 256; i++) {
            int kk = threadIdx.x + i * 256;
            float cs = g_cs[kk];
            float pre = ema_cs[kk] * DECAY + ONE_MINUS_DECAY * cs;
            float p = cs * (1.0f / (float)NTOK);
            s_pre += (double)pre;
            s_ent += (double)(p * logf(p + 1e-10f));
        }
        __shared__ double shp[8], she[8];
        int l2 = threadIdx.x & 31, w2 = threadIdx.x >> 5;
        #pragma unroll
        for (int o = 16; o; o >>= 1) {
            s_pre += __shfl_down_sync(0xffffffffu, s_pre, o);
            s_ent += __shfl_down_sync(0xffffffffu, s_ent, o);
        }
        if (l2 == 0) { shp[w2] = s_pre; she[w2] = s_ent; }
        __syncthreads();
        if (w2 == 0 && l2 < 8) {
            double vp = shp[l2], ve = she[l2];
            #pragma unroll
            for (int o = 4; o; o >>= 1) {
                vp += __shfl_down_sync(0xffu, vp, o);
                ve += __shfl_down_sync(0xffu, ve, o);
            }
            if (l2 == 0) { g_tot_pre = vp; g_tot_ent = ve; }
        }
    }
}

// ---------------------------------------------------------------------------
// K3: EMA updates + new_cs + loss/perplexity finalize (fused).
// ---------------------------------------------------------------------------
__global__ void k_ema(const float* __restrict__ ema_cs,
                      const float* __restrict__ ema_w,
                      float* __restrict__ out) {
    size_t gi = (size_t)blockIdx.x * blockDim.x + threadIdx.x;
    int k = (int)(gi >> 8);

    float cs = g_cs[k];
    float pre = ema_cs[k] * DECAY + ONE_MINUS_DECAY * cs;
    float ntot = (float)g_tot_pre;
    float denom = ntot + (float)KCODE * EPS;
    float ncs = (pre + EPS) / denom * ntot;

    float2 w = *(const float2*)(ema_w + gi * 2);
    float2 d = *(const float2*)(g_dw + gi * 2);
    float2 ew;
    ew.x = w.x * DECAY + ONE_MINUS_DECAY * d.x;
    ew.y = w.y * DECAY + ONE_MINUS_DECAY * d.y;
    *(float2*)(out + OW + gi * 2) = ew;
    float2 eb;
    eb.x = ew.x / ncs; eb.y = ew.y / ncs;
    *(float2*)(out + OE + gi * 2) = eb;

    if ((gi & 255) == 0) out[OC + k] = ncs;
    if (gi == 0) {
        out[OL] = (float)(COMMIT * g_loss / ((double)NTOK * (double)DDIM));
        out[OP] = (float)exp(-g_tot_ent);
    }
}

// ---------------------------------------------------------------------------
extern "C" void kernel_launch(void* const* d_in, const int* in_sizes, int n_in,
                              void* d_out, int out_size) {
    const float* X   = (const float*)d_in[0];
    const float* E   = (const float*)d_in[1];
    const float* ECS = (const float*)d_in[2];
    const float* EW  = (const float*)d_in[3];
    float* out = (float*)d_out;

    cudaFuncSetAttribute(k_gemm, cudaFuncAttributeMaxDynamicSharedMemorySize, GEMM_SMEM);

    k_init<<<KCODE + XBLOCKS, 256>>>(E, X);
    k_gemm<<<NCTA, 256, GEMM_SMEM>>>();
    k_refine<<<REFINE_BLOCKS, 256>>>(X, E, ECS, out);
    k_ema<<<(KCODE * DDIM / 2) / 256, 256>>>(ECS, EW, out);
}

// round 17
// speedup vs baseline: 1.0075x; 1.0075x over previous
#include <cuda_runtime.h>
#include <cuda_bf16.h>
#include <math.h>
#include <stdint.h>

// ---------------------------------------------------------------------------
// VectorQuantizerEMA (N=32768, K=8192, D=512)
// bf16 mma.sync GEMM (exact -|e|^2/2 in acc init) + global top-4 exact
// rescore with fused scatter. R17: R15 structure + widened k_ema.
// ---------------------------------------------------------------------------
#define NTOK 32768
#define KCODE 8192
#define DDIM 512

#define DECAY 0.99f
#define ONE_MINUS_DECAY 0.01f
#define EPS 1e-5f
#define COMMIT 0.25f

#define OQ  ((size_t)0)
#define OL  ((size_t)(NTOK) * DDIM)
#define OP  (OL + 1)
#define OE  (OP + 1)
#define OC  (OE + (size_t)KCODE * DDIM)
#define OW  (OC + KCODE)

// ------------------------- device scratch (no alloc) -----------------------
__device__ float                        g_halfE2[KCODE];
__device__ float                        g_cs[KCODE];
__device__ __align__(256) float         g_dw[(size_t)KCODE * DDIM];
__device__ double                       g_loss;
__device__ double                       g_tot_pre;
__device__ double                       g_tot_ent;
__device__ __align__(256) __nv_bfloat16 g_xb[(size_t)NTOK * DDIM];
__device__ __align__(256) __nv_bfloat16 g_eb[(size_t)KCODE * DDIM];
__device__ float4                       g_cand[(size_t)NTOK * 64]; // [token][ct]

// ------------------------- helpers -----------------------------------------
__device__ __forceinline__ uint32_t smem_u32(const void* p) {
    uint32_t a;
    asm("{ .reg .u64 t; cvta.to.shared.u64 t, %1; cvt.u32.u64 %0, t; }" : "=r"(a) : "l"(p));
    return a;
}
__device__ __forceinline__ void cp16(uint32_t dst, const void* src) {
    asm volatile("cp.async.cg.shared.global [%0], [%1], 16;" :: "r"(dst), "l"(src));
}
#define CP_COMMIT() asm volatile("cp.async.commit_group;" ::: "memory")

__device__ __forceinline__ void ldm_x4(uint32_t addr, uint32_t& r0, uint32_t& r1,
                                       uint32_t& r2, uint32_t& r3) {
    asm volatile("ldmatrix.sync.aligned.m8n8.x4.shared.b16 {%0,%1,%2,%3}, [%4];"
                 : "=r"(r0), "=r"(r1), "=r"(r2), "=r"(r3) : "r"(addr));
}
__device__ __forceinline__ void mma16816(float* d, const uint32_t* a, const uint32_t* b) {
    asm volatile("mma.sync.aligned.m16n8k16.row.col.f32.bf16.bf16.f32 "
                 "{%0,%1,%2,%3}, {%4,%5,%6,%7}, {%8,%9}, {%0,%1,%2,%3};"
                 : "+f"(d[0]), "+f"(d[1]), "+f"(d[2]), "+f"(d[3])
                 : "r"(a[0]), "r"(a[1]), "r"(a[2]), "r"(a[3]), "r"(b[0]), "r"(b[1]));
}
// vectorized global reduction (sm_90+): 1 REDG op for 4 floats
__device__ __forceinline__ void redg_v4(float* ptr, float a, float b, float c, float d) {
    asm volatile("red.global.add.v4.f32 [%0], {%1, %2, %3, %4};"
                 :: "l"(ptr), "f"(a), "f"(b), "f"(c), "f"(d) : "memory");
}
__device__ __forceinline__ void merge2(float& t1v, int& t1i, float& t2v, int& t2i,
                                       float o1v, int o1i, float o2v, int o2i) {
    if (o1v > t1v) {
        float n2v = t1v; int n2i = t1i;
        if (o2v > n2v) { n2v = o2v; n2i = o2i; }
        t1v = o1v; t1i = o1i; t2v = n2v; t2i = n2i;
    } else if (o1v > t2v) {
        t2v = o1v; t2i = o1i;
    }
}
__device__ __forceinline__ void ins4(float* v, int* ix, float ov, int oi) {
    if (ov > v[3]) {
        if (ov > v[2]) {
            v[3] = v[2]; ix[3] = ix[2];
            if (ov > v[1]) {
                v[2] = v[1]; ix[2] = ix[1];
                if (ov > v[0]) { v[1] = v[0]; ix[1] = ix[0]; v[0] = ov; ix[0] = oi; }
                else { v[1] = ov; ix[1] = oi; }
            } else { v[2] = ov; ix[2] = oi; }
        } else { v[3] = ov; ix[3] = oi; }
    }
}

// ---------------------------------------------------------------------------
// K0: merged init. Blocks [0, KCODE): E->bf16 + half-norms + zero scratch.
//     Blocks [KCODE, ...): X->bf16 (float4 wide).
// ---------------------------------------------------------------------------
#define XBLOCKS ((NTOK * DDIM / 4) / 256)   // 16384

__global__ void k_init(const float* __restrict__ E, const float* __restrict__ X) {
    int b = blockIdx.x;
    int t = threadIdx.x;
    if (b < KCODE) {
        int k = b;
        const float* row = E + (size_t)k * DDIM;
        float e0 = row[t], e1 = row[t + 256];

        g_eb[(size_t)k * DDIM + t]       = __float2bfloat16_rn(e0);
        g_eb[(size_t)k * DDIM + t + 256] = __float2bfloat16_rn(e1);

        float s = e0 * e0 + e1 * e1;
        __shared__ float sh[8];
        int lane = t & 31, w = t >> 5;
        #pragma unroll
        for (int o = 16; o; o >>= 1) s += __shfl_down_sync(0xffffffffu, s, o);
        if (lane == 0) sh[w] = s;
        __syncthreads();
        if (w == 0) {
            float v = (lane < 8) ? sh[lane] : 0.f;
            #pragma unroll
            for (int o = 4; o; o >>= 1) v += __shfl_down_sync(0xffffffffu, v, o);
            if (lane == 0) g_halfE2[k] = 0.5f * v;
        }
        float* dwr = g_dw + (size_t)k * DDIM;
        dwr[t] = 0.f;
        dwr[t + 256] = 0.f;
        if (t == 0) g_cs[k] = 0.f;
        if (k == 0 && t == 0) { g_loss = 0.0; g_tot_pre = 0.0; g_tot_ent = 0.0; }
    } else {
        size_t i = (size_t)(b - KCODE) * 256 + t;     // float4 index
        float4 x = *(const float4*)(X + i * 4);
        __nv_bfloat162 lo = __floats2bfloat162_rn(x.x, x.y);
        __nv_bfloat162 hi = __floats2bfloat162_rn(x.z, x.w);
        uint2 o;
        o.x = *(uint32_t*)&lo;
        o.y = *(uint32_t*)&hi;
        *(uint2*)(g_xb + i * 4) = o;
    }
}

// ---------------------------------------------------------------------------
// K1: persistent bf16 GEMM + per-tile top-2. (R8 structure, unchanged)
// ---------------------------------------------------------------------------
#define BM 128
#define BN 128
#define BK 32
#define KCH 16
#define NITEMS (256 * 64)
#define NCTA 296
#define SROW 40                      // bf16 stride (32 + 8 pad) = 80 B
#define STAGE_A (BM * SROW * 2)      // 10240 B
#define STAGE_SZ (2 * STAGE_A)       // 20480 B
#define NSTAGE 4
#define RED_OFF (NSTAGE * STAGE_SZ)
#define GEMM_SMEM (RED_OFF + 4096)   // 86016 B

__device__ __forceinline__ void load_flat(int gflat, int i0, uint32_t sb, int tid) {
    const int item = i0 + (gflat >> 4);
    const int kc = gflat & 15;
    const int m0 = (item >> 6) * BM;
    const int n0 = (item & 63) * BN;
    const int koff = kc * BK;
    const uint32_t stA = sb + (gflat & 3) * STAGE_SZ;
    const uint32_t stB = stA + STAGE_A;
    #pragma unroll
    for (int i = 0; i < 2; i++) {
        int idx = tid + i * 256;
        int row = idx >> 2, c = idx & 3;
        cp16(stA + row * (SROW * 2) + c * 16,
             g_xb + (size_t)(m0 + row) * DDIM + koff + c * 8);
        cp16(stB + row * (SROW * 2) + c * 16,
             g_eb + (size_t)(n0 + row) * DDIM + koff + c * 8);
    }
    CP_COMMIT();
}

__global__ __launch_bounds__(256, 2)
void k_gemm() {
    extern __shared__ char smem[];
    const uint32_t sb = smem_u32(smem);
    const int tid = threadIdx.x;
    const int wid = tid >> 5;
    const int lane = tid & 31;
    const int wm = wid >> 1;
    const int wn = wid & 1;
    const int bid = blockIdx.x;

    const int base = NITEMS / NCTA;              // 55
    const int rem  = NITEMS - base * NCTA;       // 104
    const int i0   = bid * base + (bid < rem ? bid : rem);
    const int cnt  = base + (bid < rem ? 1 : 0);
    const int T    = cnt * KCH;

    const uint32_t a_off = (uint32_t)(wm * 32 + (lane & 15)) * (SROW * 2) + (lane >> 4) * 16;
    const uint32_t b_row = (uint32_t)(wn * 64 + (lane & 7) + ((lane >> 4) << 3));
    const uint32_t b_off = b_row * (SROW * 2) + ((lane >> 3) & 1) * 16;

    load_flat(0, i0, sb, tid);
    load_flat(1, i0, sb, tid);
    load_flat(2, i0, sb, tid);

    float acc[2][8][4];

    for (int g = 0; g < T; ++g) {
        const int kc = g & 15;
        const int item = i0 + (g >> 4);
        const int n0 = (item & 63) * BN;

        if (kc == 0) {
            #pragma unroll
            for (int nf = 0; nf < 8; nf++) {
                int col = n0 + wn * 64 + nf * 8 + (lane & 3) * 2;
                float2 h = *(const float2*)(&g_halfE2[col]);
                acc[0][nf][0] = -h.x; acc[0][nf][1] = -h.y;
                acc[0][nf][2] = -h.x; acc[0][nf][3] = -h.y;
                acc[1][nf][0] = -h.x; acc[1][nf][1] = -h.y;
                acc[1][nf][2] = -h.x; acc[1][nf][3] = -h.y;
            }
        }

        const int pa = T - 1 - g;
        if (pa >= 2)      asm volatile("cp.async.wait_group 2;" ::: "memory");
        else if (pa == 1) asm volatile("cp.async.wait_group 1;" ::: "memory");
        else              asm volatile("cp.async.wait_group 0;" ::: "memory");
        __syncthreads();

        const uint32_t stA = sb + (g & 3) * STAGE_SZ;
        const uint32_t stB = stA + STAGE_A;
        #pragma unroll
        for (int ks = 0; ks < 2; ks++) {
            uint32_t a[2][4];
            ldm_x4(stA + a_off + ks * 32, a[0][0], a[0][1], a[0][2], a[0][3]);
            ldm_x4(stA + a_off + ks * 32 + 16 * (SROW * 2),
                   a[1][0], a[1][1], a[1][2], a[1][3]);
            uint32_t b[8][2];
            #pragma unroll
            for (int np = 0; np < 4; np++) {
                uint32_t r0, r1, r2, r3;
                ldm_x4(stB + b_off + ks * 32 + np * (16 * SROW * 2), r0, r1, r2, r3);
                b[np * 2][0] = r0; b[np * 2][1] = r1;
                b[np * 2 + 1][0] = r2; b[np * 2 + 1][1] = r3;
            }
            #pragma unroll
            for (int mf = 0; mf < 2; mf++)
                #pragma unroll
                for (int nf = 0; nf < 8; nf++)
                    mma16816(acc[mf][nf], a[mf], b[nf]);
        }
        if (g + 3 < T) load_flat(g + 3, i0, sb, tid);

        if (kc == KCH - 1) {
            const int m0 = (item >> 6) * BM;
            const int ct = item & 63;
            float t1v[4], t2v[4];
            int   t1i[4], t2i[4];
            #pragma unroll
            for (int s = 0; s < 4; s++) { t1v[s] = -3.0e38f; t2v[s] = -3.0e38f; t1i[s] = 0; t2i[s] = 0; }
            #pragma unroll
            for (int mf = 0; mf < 2; mf++)
                #pragma unroll
                for (int h = 0; h < 2; h++) {
                    int s = mf * 2 + h;
                    #pragma unroll
                    for (int nf = 0; nf < 8; nf++) {
                        int colb = n0 + wn * 64 + nf * 8 + (lane & 3) * 2;
                        float v0 = acc[mf][nf][h * 2 + 0];
                        float v1 = acc[mf][nf][h * 2 + 1];
                        if (v0 > t1v[s]) { t2v[s] = t1v[s]; t2i[s] = t1i[s]; t1v[s] = v0; t1i[s] = colb; }
                        else if (v0 > t2v[s]) { t2v[s] = v0; t2i[s] = colb; }
                        if (v1 > t1v[s]) { t2v[s] = t1v[s]; t2i[s] = t1i[s]; t1v[s] = v1; t1i[s] = colb + 1; }
                        else if (v1 > t2v[s]) { t2v[s] = v1; t2i[s] = colb + 1; }
                    }
                }
            #pragma unroll
            for (int s = 0; s < 4; s++) {
                #pragma unroll
                for (int d = 1; d <= 2; d <<= 1) {
                    float o1v = __shfl_xor_sync(0xffffffffu, t1v[s], d);
                    int   o1i = __shfl_xor_sync(0xffffffffu, t1i[s], d);
                    float o2v = __shfl_xor_sync(0xffffffffu, t2v[s], d);
                    int   o2i = __shfl_xor_sync(0xffffffffu, t2i[s], d);
                    merge2(t1v[s], t1i[s], t2v[s], t2i[s], o1v, o1i, o2v, o2i);
                }
            }
            __syncthreads();
            float* c_v = (float*)(smem + RED_OFF);            // [128][2][2]
            int*   c_i = (int*)(smem + RED_OFF + 2048);       // [128][2][2]
            if ((lane & 3) == 0) {
                #pragma unroll
                for (int s = 0; s < 4; s++) {
                    int mf = s >> 1, h = s & 1;
                    int row = wm * 32 + mf * 16 + h * 8 + (lane >> 2);
                    c_v[(row * 2 + wn) * 2 + 0] = t1v[s];
                    c_v[(row * 2 + wn) * 2 + 1] = t2v[s];
                    c_i[(row * 2 + wn) * 2 + 0] = t1i[s];
                    c_i[(row * 2 + wn) * 2 + 1] = t2i[s];
                }
            }
            __syncthreads();
            if (tid < BM) {
                float v1 = c_v[(tid * 2) * 2 + 0], v2 = c_v[(tid * 2) * 2 + 1];
                int   i1 = c_i[(tid * 2) * 2 + 0], i2 = c_i[(tid * 2) * 2 + 1];
                merge2(v1, i1, v2, i2,
                       c_v[(tid * 2 + 1) * 2 + 0], c_i[(tid * 2 + 1) * 2 + 0],
                       c_v[(tid * 2 + 1) * 2 + 1], c_i[(tid * 2 + 1) * 2 + 1]);
                g_cand[(size_t)(m0 + tid) * 64 + ct] =
                    make_float4(v1, v2, __int_as_float(i1), __int_as_float(i2));
            }
        }
    }
}

// ---------------------------------------------------------------------------
// K1b: merge 64 tile-candidates -> global top-4, exact fp32 rescore, then
// fused scatter. One warp per token. Vectorized I/O + red.global.v4.f32.
// ---------------------------------------------------------------------------
__global__ void k_refine(const float* __restrict__ X, const float* __restrict__ E,
                         float* __restrict__ out) {
    const int n = blockIdx.x * 8 + (threadIdx.x >> 5);
    const int lane = threadIdx.x & 31;

    float4 cA = g_cand[(size_t)n * 64 + lane];
    float4 cB = g_cand[(size_t)n * 64 + lane + 32];

    float v[4]; int ix[4];
    v[0] = -3.0e38f; v[1] = -3.0e38f; v[2] = -3.0e38f; v[3] = -3.0e38f;
    ix[0] = ix[1] = ix[2] = ix[3] = 0;
    ins4(v, ix, cA.x, __float_as_int(cA.z));
    ins4(v, ix, cA.y, __float_as_int(cA.w));
    ins4(v, ix, cB.x, __float_as_int(cB.z));
    ins4(v, ix, cB.y, __float_as_int(cB.w));

    #pragma unroll
    for (int d = 16; d; d >>= 1) {
        float ov[4]; int oi[4];
        #pragma unroll
        for (int s = 0; s < 4; s++) {
            ov[s] = __shfl_xor_sync(0xffffffffu, v[s], d);
            oi[s] = __shfl_xor_sync(0xffffffffu, ix[s], d);
        }
        #pragma unroll
        for (int s = 0; s < 4; s++) ins4(v, ix, ov[s], oi[s]);
    }

    float4 xr[4];
    const float* x = X + (size_t)n * DDIM;
    #pragma unroll
    for (int i = 0; i < 4; i++) xr[i] = *(const float4*)(x + lane * 4 + i * 128);

    float bestv = -3.0e38f; int besti = 0x7fffffff;
    #pragma unroll
    for (int c = 0; c < 4; c++) {
        const float* e = E + (size_t)ix[c] * DDIM;
        float s = 0.f;
        #pragma unroll
        for (int i = 0; i < 4; i++) {
            float4 ev = *(const float4*)(e + lane * 4 + i * 128);
            s = fmaf(xr[i].x, ev.x, s);
            s = fmaf(xr[i].y, ev.y, s);
            s = fmaf(xr[i].z, ev.z, s);
            s = fmaf(xr[i].w, ev.w, s);
        }
        #pragma unroll
        for (int o = 16; o; o >>= 1) s += __shfl_xor_sync(0xffffffffu, s, o);
        s -= g_halfE2[ix[c]];
        if (s > bestv || (s == bestv && ix[c] < besti)) { bestv = s; besti = ix[c]; }
    }

    // ---- fused scatter ----
    const int k = besti;
    const float* e = E + (size_t)k * DDIM;
    float ls = 0.f;
    #pragma unroll
    for (int i = 0; i < 4; i++) {
        float4 q = *(const float4*)(e + lane * 4 + i * 128);
        float4 o;
        float dx = q.x - xr[i].x, dy = q.y - xr[i].y;
        float dz = q.z - xr[i].z, dw = q.w - xr[i].w;
        o.x = xr[i].x + dx; o.y = xr[i].y + dy;
        o.z = xr[i].z + dz; o.w = xr[i].w + dw;
        *(float4*)(out + OQ + (size_t)n * DDIM + lane * 4 + i * 128) = o;
        ls = fmaf(dx, dx, ls); ls = fmaf(dy, dy, ls);
        ls = fmaf(dz, dz, ls); ls = fmaf(dw, dw, ls);
        redg_v4(&g_dw[(size_t)k * DDIM + lane * 4 + i * 128],
                xr[i].x, xr[i].y, xr[i].z, xr[i].w);
    }
    #pragma unroll
    for (int o = 16; o; o >>= 1) ls += __shfl_xor_sync(0xffffffffu, ls, o);
    if (lane == 0) {
        atomicAdd(&g_loss, (double)ls);
        atomicAdd(&g_cs[k], 1.0f);
    }
}

// ---------------------------------------------------------------------------
// K2: parallel stats reduce: Sum(pre), Sum(entropy) into double atomics.
// ---------------------------------------------------------------------------
__global__ void k_reduce(const float* __restrict__ ema_cs) {
    int k = blockIdx.x * 256 + threadIdx.x;
    float cs = g_cs[k];
    float pre = ema_cs[k] * DECAY + ONE_MINUS_DECAY * cs;
    float p = cs * (1.0f / (float)NTOK);
    double s_pre = (double)pre;
    double s_ent = (double)(p * logf(p + 1e-10f));

    __shared__ double shp[8], she[8];
    int lane = threadIdx.x & 31, w = threadIdx.x >> 5;
    #pragma unroll
    for (int o = 16; o; o >>= 1) {
        s_pre += __shfl_down_sync(0xffffffffu, s_pre, o);
        s_ent += __shfl_down_sync(0xffffffffu, s_ent, o);
    }
    if (lane == 0) { shp[w] = s_pre; she[w] = s_ent; }
    __syncthreads();
    if (w == 0 && lane < 8) {
        double vp = shp[lane], ve = she[lane];
        #pragma unroll
        for (int o = 4; o; o >>= 1) {
            vp += __shfl_down_sync(0xffu, vp, o);
            ve += __shfl_down_sync(0xffu, ve, o);
        }
        if (lane == 0) {
            atomicAdd(&g_tot_pre, vp);
            atomicAdd(&g_tot_ent, ve);
        }
    }
}

// ---------------------------------------------------------------------------
// K3: EMA updates + new_cs + loss/perplexity finalize (fused).
// 4 floats per thread: float4 loads, paired float2 stores (OE/OW 8B-aligned).
// ---------------------------------------------------------------------------
__global__ void k_ema(const float* __restrict__ ema_cs,
                      const float* __restrict__ ema_w,
                      float* __restrict__ out) {
    size_t gi = (size_t)blockIdx.x * blockDim.x + threadIdx.x;  // float4 index
    int k = (int)(gi >> 7);   // 128 float4 per row

    float cs = g_cs[k];
    float pre = ema_cs[k] * DECAY + ONE_MINUS_DECAY * cs;
    float ntot = (float)g_tot_pre;
    float denom = ntot + (float)KCODE * EPS;
    float ncs = (pre + EPS) / denom * ntot;
    float rinv = 1.0f / ncs;

    float4 w = *(const float4*)(ema_w + gi * 4);
    float4 d = *(const float4*)(g_dw + gi * 4);
    float4 ew;
    ew.x = w.x * DECAY + ONE_MINUS_DECAY * d.x;
    ew.y = w.y * DECAY + ONE_MINUS_DECAY * d.y;
    ew.z = w.z * DECAY + ONE_MINUS_DECAY * d.z;
    ew.w = w.w * DECAY + ONE_MINUS_DECAY * d.w;
    float2 ew0 = make_float2(ew.x, ew.y);
    float2 ew1 = make_float2(ew.z, ew.w);
    *(float2*)(out + OW + gi * 4)     = ew0;
    *(float2*)(out + OW + gi * 4 + 2) = ew1;
    float2 eb0 = make_float2(ew.x * rinv, ew.y * rinv);
    float2 eb1 = make_float2(ew.z * rinv, ew.w * rinv);
    *(float2*)(out + OE + gi * 4)     = eb0;
    *(float2*)(out + OE + gi * 4 + 2) = eb1;

    if ((gi & 127) == 0) out[OC + k] = ncs;
    if (gi == 0) {
        out[OL] = (float)(COMMIT * g_loss / ((double)NTOK * (double)DDIM));
        out[OP] = (float)exp(-g_tot_ent);
    }
}

// ---------------------------------------------------------------------------
extern "C" void kernel_launch(void* const* d_in, const int* in_sizes, int n_in,
                              void* d_out, int out_size) {
    const float* X   = (const float*)d_in[0];
    const float* E   = (const float*)d_in[1];
    const float* ECS = (const float*)d_in[2];
    const float* EW  = (const float*)d_in[3];
    float* out = (float*)d_out;

    cudaFuncSetAttribute(k_gemm, cudaFuncAttributeMaxDynamicSharedMemorySize, GEMM_SMEM);

    k_init<<<KCODE + XBLOCKS, 256>>>(E, X);
    k_gemm<<<NCTA, 256, GEMM_SMEM>>>();
    k_refine<<<NTOK / 8, 256>>>(X, E, out);
    k_reduce<<<KCODE / 256, 256>>>(ECS);
    k_ema<<<(KCODE * DDIM / 4) / 256, 256>>>(ECS, EW, out);
}